// round 8
// baseline (speedup 1.0000x reference)
#include <cuda_runtime.h>
#include <cstdint>

// ---------------- problem constants ----------------
#define B_TOT   16384
#define T_HOR   128
#define F_IN    29
#define K_HID   512
#define BTILE   64
#define NTH     256
#define NCTAS   (B_TOT / BTILE)     // 256
#define TF_STR  (T_HOR * F_IN)      // 3712 floats per batch row

// X stage buffer: 64 rows x stride 36 (pad -> conflict-free LDS), double-buffered, raw fp32
#define XSTRIDE 36
#define XBUF    (BTILE * XSTRIDE)   // 2304 floats
#define XELEMS  (BTILE * F_IN)      // 1856 floats per step

// ---------------- shared memory layout ----------------
// B packed as two float4 arrays (kc01 and kc23), 2048 float4 each = 64KB total
#define SM_B4A_OFF  0
#define SM_B4B_OFF  32768
#define SM_CP_OFF   65536                         // 256 x float4 = 4KB
#define SM_PART_OFF (SM_CP_OFF + 4096)            // 69632: 2 x 256 floats = 2KB
#define SM_X_OFF    (SM_PART_OFF + 2048)          // 71680: 2 x 2304 floats = 18432B
#define SM_TOTAL    (SM_X_OFF + 2 * XBUF * 4)     // 90112 bytes (fits 2 CTAs/SM)

static __device__ __forceinline__ uint32_t tf32r(float x) {
    uint32_t r;
    asm("cvt.rna.tf32.f32 %0, %1;" : "=r"(r) : "f"(x));
    return r;
}

static __device__ __forceinline__ float tanh_fast(float z) {
    float h;
    asm("tanh.approx.f32 %0, %1;" : "=f"(h) : "f"(z));
    return h;
}

static __device__ __forceinline__ uint32_t smem_u32(const void* p) {
    uint32_t a;
    asm("{ .reg .u64 t; cvta.to.shared.u64 t, %1; cvt.u32.u64 %0, t; }"
        : "=r"(a) : "l"(p));
    return a;
}

#define CP_ASYNC4(dst, src) \
    asm volatile("cp.async.ca.shared.global [%0], [%1], 4;" :: "r"(dst), "l"(src))
#define CP_COMMIT() asm volatile("cp.async.commit_group;" ::: "memory")
#define CP_WAIT0()  asm volatile("cp.async.wait_group 0;" ::: "memory")

// non-volatile: let ptxas schedule/interleave freely
#define MMA_TF32(d0, d1, d2, d3, a0, a1, a2, a3, b0, b1)                       \
    asm("mma.sync.aligned.m16n8k8.row.col.f32.tf32.tf32.f32 "                  \
        "{%0,%1,%2,%3}, {%4,%5,%6,%7}, {%8,%9}, {%0,%1,%2,%3};"                \
        : "+f"(d0), "+f"(d1), "+f"(d2), "+f"(d3)                               \
        : "r"(a0), "r"(a1), "r"(a2), "r"(a3), "r"(b0), "r"(b1))

// fast div by 29 for j < 16384:  row = (j*565) >> 14
static __device__ __forceinline__ int div29(int j) { return (j * 565) >> 14; }

// Load one A fragment set (16 tf32 regs) for rows (rA, rA+8) from the raw-fp32 X stage.
// Cols: kc*8+lq and kc*8+lq+4. For kc==3, c1 = 28+lq:
//   lq==0 -> X col 28;  lq==1/2/3 -> feedback fb0/fb1/fb2 (pre-rounded tf32).
static __device__ __forceinline__ void loadA_sm(uint32_t a[16], const float* __restrict__ Xc,
                                                int rA, int lq, uint32_t fbA, uint32_t fbB) {
    const float* xA = Xc + rA * XSTRIDE;
    const float* xB = xA + 8 * XSTRIDE;
    #pragma unroll
    for (int kc = 0; kc < 4; ++kc) {
        const int c0 = kc * 8 + lq;          // <= 27
        a[kc * 4 + 0] = tf32r(xA[c0]);
        a[kc * 4 + 1] = tf32r(xB[c0]);
        if (kc < 3) {
            const int c1 = c0 + 4;           // <= 23
            a[kc * 4 + 2] = tf32r(xA[c1]);
            a[kc * 4 + 3] = tf32r(xB[c1]);
        }
    }
    if (lq == 0) {
        a[14] = tf32r(xA[28]);
        a[15] = tf32r(xB[28]);
    } else {
        a[14] = fbA;
        a[15] = fbB;
    }
}

__global__ void __launch_bounds__(NTH, 2)
narx_kernel(const float* __restrict__ X, const float* __restrict__ y0,
            const float* __restrict__ W1, const float* __restrict__ b1,
            const float* __restrict__ W2, const float* __restrict__ b2,
            float* __restrict__ out)
{
    extern __shared__ char smem[];
    float4* __restrict__ B4a  = (float4*)(smem + SM_B4A_OFF);
    float4* __restrict__ B4b  = (float4*)(smem + SM_B4B_OFF);
    float4* __restrict__ cp4  = (float4*)(smem + SM_CP_OFF);
    float*  __restrict__ part = (float*)(smem + SM_PART_OFF);
    float*  __restrict__ Xs   = (float*)(smem + SM_X_OFF);
    const uint32_t XsAddr = smem_u32(Xs);

    const int tid  = threadIdx.x;
    const int w    = tid >> 5;
    const int lane = tid & 31;
    const int lq   = lane & 3;       // quad lane (k / col-pair selector)
    const int lg   = lane >> 2;      // group (row selector)
    const int g    = w & 1;          // row group: rows g*32 .. g*32+31
    const int q    = w >> 1;         // column quarter: cols q*128 .. q*128+127
    const int ctaB0 = blockIdx.x * BTILE;

    // --- stage B operand packed as float4 pairs ---
    // entry (h, ntg, lane): col = ntg*8 + (lane>>2), p = lane&3, kc = 2h / 2h+1:
    //   float4( W1[(2h)*8+p][col], W1[(2h)*8+p+4][col],
    //           W1[(2h+1)*8+p][col], W1[(2h+1)*8+p+4][col] )
    for (int idx = tid; idx < 4096; idx += NTH) {
        const int hh = idx >> 11, rem = idx & 2047;
        const int ln = rem & 31;
        const int col = (rem >> 5) * 8 + (ln >> 2);
        const int p = ln & 3;
        const int kc0 = 2 * hh, kc1 = kc0 + 1;
        float4 fv;
        fv.x = __uint_as_float(tf32r(W1[(kc0 * 8 + p) * K_HID + col]));
        fv.y = __uint_as_float(tf32r(W1[(kc0 * 8 + p + 4) * K_HID + col]));
        fv.z = __uint_as_float(tf32r(W1[(kc1 * 8 + p) * K_HID + col]));
        fv.w = __uint_as_float(tf32r(W1[(kc1 * 8 + p + 4) * K_HID + col]));
        if (hh == 0) B4a[rem] = fv; else B4b[rem] = fv;
    }
    // --- per-col-pair constants: (b1[c0], b1[c1], w2[c0], w2[c1]) ---
    for (int p = tid; p < K_HID / 2; p += NTH) {
        float4 c;
        c.x = b1[2 * p];
        c.y = b1[2 * p + 1];
        c.z = W2[2 * p];
        c.w = W2[2 * p + 1];
        cp4[p] = c;
    }
    // --- stage X(0) into buffer 0 via cp.async (raw fp32) ---
    {
        const float* __restrict__ src = X + (size_t)ctaB0 * TF_STR;
        #pragma unroll
        for (int k = 0; k < 8; ++k) {
            const int j = tid + k * NTH;
            if (j < XELEMS) {
                const int row = div29(j), col = j - row * F_IN;
                CP_ASYNC4(XsAddr + (uint32_t)(row * XSTRIDE + col) * 4,
                          src + (size_t)row * TF_STR + col);
            }
        }
        CP_COMMIT();
    }
    CP_WAIT0();
    __syncthreads();

    // --- per-thread row bindings: 4 rows (rowL0 +0/+8/+16/+24) ---
    const int rowL0 = g * 32 + lg;
    const int rowG0 = ctaB0 + rowL0;
    float* __restrict__ outBase = out + (size_t)rowG0 * T_HOR;

    const float b2v = b2[0];

    float f0a = y0[rowG0 * 3 + 0],        f1a = y0[rowG0 * 3 + 1],        f2a = y0[rowG0 * 3 + 2];
    float f0b = y0[(rowG0 + 8) * 3 + 0],  f1b = y0[(rowG0 + 8) * 3 + 1],  f2b = y0[(rowG0 + 8) * 3 + 2];
    float f0c = y0[(rowG0 + 16) * 3 + 0], f1c = y0[(rowG0 + 16) * 3 + 1], f2c = y0[(rowG0 + 16) * 3 + 2];
    float f0d = y0[(rowG0 + 24) * 3 + 0], f1d = y0[(rowG0 + 24) * 3 + 1], f2d = y0[(rowG0 + 24) * 3 + 2];
    uint32_t fbA = tf32r((lq == 1) ? f0a : (lq == 2) ? f1a : f2a);
    uint32_t fbB = tf32r((lq == 1) ? f0b : (lq == 2) ? f1b : f2b);
    uint32_t fbC = tf32r((lq == 1) ? f0c : (lq == 2) ? f1c : f2c);
    uint32_t fbD = tf32r((lq == 1) ? f0d : (lq == 2) ? f1d : f2d);

    const int ntOfs = q * 16;               // this warp's n-tile offset (16 tiles = 128 cols)

    for (int t = 0; t < T_HOR; ++t) {
        const float* Xc = Xs + (t & 1) * XBUF;

        uint32_t a0[16], a1[16];
        loadA_sm(a0, Xc, rowL0, lq, fbA, fbB);
        loadA_sm(a1, Xc, rowL0 + 16, lq, fbC, fbD);

        // fire next step's X stage via cp.async; completion hidden under the nt loop
        const bool pf = (t + 1) < T_HOR;
        if (pf) {
            const float* __restrict__ src = X + (size_t)ctaB0 * TF_STR + (t + 1) * F_IN;
            const uint32_t dstBase = XsAddr + (uint32_t)(((t + 1) & 1) * XBUF) * 4;
            #pragma unroll
            for (int k = 0; k < 8; ++k) {
                const int j = tid + k * NTH;
                if (j < XELEMS) {
                    const int row = div29(j), col = j - row * F_IN;
                    CP_ASYNC4(dstBase + (uint32_t)(row * XSTRIDE + col) * 4,
                              src + (size_t)row * TF_STR + col);
                }
            }
            CP_COMMIT();
        }

        float dotA = 0.0f, dotB = 0.0f, dotC = 0.0f, dotD = 0.0f;

        #pragma unroll 4
        for (int nt = 0; nt < 16; ++nt) {
            const int ntg = ntOfs + nt;      // global n-tile (0..63)
            const float4 qc = cp4[ntg * 4 + lq];
            const float4 ba = B4a[ntg * 32 + lane];   // kc0, kc1
            const float4 bb = B4b[ntg * 32 + lane];   // kc2, kc3
            float d0 = qc.x, d1 = qc.y, d2 = qc.x, d3 = qc.y;   // set0 (bias-init)
            float e0 = qc.x, e1 = qc.y, e2 = qc.x, e3 = qc.y;   // set1
            MMA_TF32(d0, d1, d2, d3, a0[0],  a0[1],  a0[2],  a0[3],
                     __float_as_uint(ba.x), __float_as_uint(ba.y));
            MMA_TF32(e0, e1, e2, e3, a1[0],  a1[1],  a1[2],  a1[3],
                     __float_as_uint(ba.x), __float_as_uint(ba.y));
            MMA_TF32(d0, d1, d2, d3, a0[4],  a0[5],  a0[6],  a0[7],
                     __float_as_uint(ba.z), __float_as_uint(ba.w));
            MMA_TF32(e0, e1, e2, e3, a1[4],  a1[5],  a1[6],  a1[7],
                     __float_as_uint(ba.z), __float_as_uint(ba.w));
            MMA_TF32(d0, d1, d2, d3, a0[8],  a0[9],  a0[10], a0[11],
                     __float_as_uint(bb.x), __float_as_uint(bb.y));
            MMA_TF32(e0, e1, e2, e3, a1[8],  a1[9],  a1[10], a1[11],
                     __float_as_uint(bb.x), __float_as_uint(bb.y));
            MMA_TF32(d0, d1, d2, d3, a0[12], a0[13], a0[14], a0[15],
                     __float_as_uint(bb.z), __float_as_uint(bb.w));
            MMA_TF32(e0, e1, e2, e3, a1[12], a1[13], a1[14], a1[15],
                     __float_as_uint(bb.z), __float_as_uint(bb.w));
            dotA = fmaf(tanh_fast(d0), qc.z, dotA);
            dotA = fmaf(tanh_fast(d1), qc.w, dotA);
            dotB = fmaf(tanh_fast(d2), qc.z, dotB);
            dotB = fmaf(tanh_fast(d3), qc.w, dotB);
            dotC = fmaf(tanh_fast(e0), qc.z, dotC);
            dotC = fmaf(tanh_fast(e1), qc.w, dotC);
            dotD = fmaf(tanh_fast(e2), qc.z, dotD);
            dotD = fmaf(tanh_fast(e3), qc.w, dotD);
        }

        // quad reduce (over the 8 cols each quad member covers)
        dotA += __shfl_xor_sync(0xffffffffu, dotA, 1);
        dotA += __shfl_xor_sync(0xffffffffu, dotA, 2);
        dotB += __shfl_xor_sync(0xffffffffu, dotB, 1);
        dotB += __shfl_xor_sync(0xffffffffu, dotB, 2);
        dotC += __shfl_xor_sync(0xffffffffu, dotC, 1);
        dotC += __shfl_xor_sync(0xffffffffu, dotC, 2);
        dotD += __shfl_xor_sync(0xffffffffu, dotD, 1);
        dotD += __shfl_xor_sync(0xffffffffu, dotD, 2);

        // cross-quarter combine via double-buffered SMEM partials + one barrier
        float* pbuf = part + (t & 1) * 256;
        if (lq == 0) {
            pbuf[q * 64 + rowL0]      = dotA;
            pbuf[q * 64 + rowL0 + 8]  = dotB;
            pbuf[q * 64 + rowL0 + 16] = dotC;
            pbuf[q * 64 + rowL0 + 24] = dotD;
        }
        if (pf) CP_WAIT0();     // cp.async data arrival; cheap, already landed
        __syncthreads();
        const float predA = pbuf[rowL0]      + pbuf[64 + rowL0]      + pbuf[128 + rowL0]      + pbuf[192 + rowL0]      + b2v;
        const float predB = pbuf[rowL0 + 8]  + pbuf[64 + rowL0 + 8]  + pbuf[128 + rowL0 + 8]  + pbuf[192 + rowL0 + 8]  + b2v;
        const float predC = pbuf[rowL0 + 16] + pbuf[64 + rowL0 + 16] + pbuf[128 + rowL0 + 16] + pbuf[192 + rowL0 + 16] + b2v;
        const float predD = pbuf[rowL0 + 24] + pbuf[64 + rowL0 + 24] + pbuf[128 + rowL0 + 24] + pbuf[192 + rowL0 + 24] + b2v;
        if (q == 0 && lq == 0) {
            outBase[t]              = predA;
            outBase[8 * T_HOR + t]  = predB;
            outBase[16 * T_HOR + t] = predC;
            outBase[24 * T_HOR + t] = predD;
        }
        // shift feedback: fb2 <- fb1 <- fb0 <- pred; refresh tf32 selections
        f2a = f1a; f1a = f0a; f0a = predA;
        f2b = f1b; f1b = f0b; f0b = predB;
        f2c = f1c; f1c = f0c; f0c = predC;
        f2d = f1d; f1d = f0d; f0d = predD;
        fbA = tf32r((lq == 1) ? f0a : (lq == 2) ? f1a : f2a);
        fbB = tf32r((lq == 1) ? f0b : (lq == 2) ? f1b : f2b);
        fbC = tf32r((lq == 1) ? f0c : (lq == 2) ? f1c : f2c);
        fbD = tf32r((lq == 1) ? f0d : (lq == 2) ? f1d : f2d);
    }
}

extern "C" void kernel_launch(void* const* d_in, const int* in_sizes, int n_in,
                              void* d_out, int out_size) {
    const float* X  = (const float*)d_in[0];
    const float* y0 = (const float*)d_in[1];
    const float* W1 = (const float*)d_in[2];
    const float* b1 = (const float*)d_in[3];
    const float* W2 = (const float*)d_in[4];
    const float* b2 = (const float*)d_in[5];
    float* out = (float*)d_out;
    (void)in_sizes; (void)n_in; (void)out_size;

    cudaFuncSetAttribute(narx_kernel, cudaFuncAttributeMaxDynamicSharedMemorySize, SM_TOTAL);
    narx_kernel<<<NCTAS, NTH, SM_TOTAL>>>(X, y0, W1, b1, W2, b2, out);
}

// round 9
// speedup vs baseline: 1.2859x; 1.2859x over previous
#include <cuda_runtime.h>
#include <cuda_fp16.h>
#include <cstdint>

// ---------------- problem constants ----------------
#define B_TOT   16384
#define T_HOR   128
#define F_IN    29
#define K_HID   512
#define BTILE   64
#define NTH     256
#define NCTAS   (B_TOT / BTILE)     // 256
#define TF_STR  (T_HOR * F_IN)      // 3712 floats per batch row

// X stage: fp32, 64 rows x stride 36, double-buffered
#define XSTRIDE 36
#define XBUF    (BTILE * XSTRIDE)   // 2304 floats
#define XELEMS  (BTILE * F_IN)      // 1856 floats per step

// ---------------- shared memory layout ----------------
// B4: 64 n-tiles x 32 lanes x uint4 (8 fp16 = all 32 k for one col) = 32KB
#define SM_B4_OFF   0
#define SM_CP_OFF   32768                         // 256 x float4 = 4KB
#define SM_PART_OFF (SM_CP_OFF + 4096)            // 36864: 2 x 256 floats = 2KB
#define SM_X_OFF    (SM_PART_OFF + 2048)          // 38912: 2 x 2304 floats = 18432B
#define SM_TOTAL    (SM_X_OFF + 2 * XBUF * 4)     // 57344 bytes (2 CTAs/SM easily)

static __device__ __forceinline__ float tanh_fast(float z) {
    float h;
    asm("tanh.approx.f32 %0, %1;" : "=f"(h) : "f"(z));
    return h;
}

// pack two floats into a f16x2 register (lo = first arg)
static __device__ __forceinline__ uint32_t h2u(float lo, float hi) {
    __half2 h = __floats2half2_rn(lo, hi);
    return *reinterpret_cast<uint32_t*>(&h);
}

// non-volatile fp16 MMA m16n8k16, fp32 accum
#define MMA_F16(d0, d1, d2, d3, a0, a1, a2, a3, b0, b1)                        \
    asm("mma.sync.aligned.m16n8k16.row.col.f32.f16.f16.f32 "                   \
        "{%0,%1,%2,%3}, {%4,%5,%6,%7}, {%8,%9}, {%0,%1,%2,%3};"                \
        : "+f"(d0), "+f"(d1), "+f"(d2), "+f"(d3)                               \
        : "r"(a0), "r"(a1), "r"(a2), "r"(a3), "r"(b0), "r"(b1))

// fast div by 29 for j < 16384
static __device__ __forceinline__ int div29(int j) { return (j * 565) >> 14; }

// Build one A fragment set (8 f16x2 regs) for rows (rA, rA+8) from the fp32 X stage.
// m16n8k16 layout: a0/a1 k=2lq,2lq+1 (rows rA/rA+8); a2/a3 k+8; a4/a5 k+16; a6/a7 k+24.
// k 28..31: lq==2 -> (x[28], fb0); lq==3 -> (fb1, fb2); lq<2 -> real X cols.
static __device__ __forceinline__ void loadA_h(uint32_t a[8], const float* __restrict__ Xc,
                                               int rA, int lq,
                                               float fb0lo, float fb0hi,
                                               uint32_t fb12lo, uint32_t fb12hi) {
    const float* xA = Xc + rA * XSTRIDE;
    const float* xB = xA + 8 * XSTRIDE;
    const int c = 2 * lq;
    a[0] = h2u(xA[c],      xA[c + 1]);
    a[1] = h2u(xB[c],      xB[c + 1]);
    a[2] = h2u(xA[c + 8],  xA[c + 9]);
    a[3] = h2u(xB[c + 8],  xB[c + 9]);
    a[4] = h2u(xA[c + 16], xA[c + 17]);
    a[5] = h2u(xB[c + 16], xB[c + 17]);
    if (lq < 2) {
        a[6] = h2u(xA[c + 24], xA[c + 25]);
        a[7] = h2u(xB[c + 24], xB[c + 25]);
    } else if (lq == 2) {
        a[6] = h2u(xA[28], fb0lo);
        a[7] = h2u(xB[28], fb0hi);
    } else {
        a[6] = fb12lo;
        a[7] = fb12hi;
    }
}

__global__ void __launch_bounds__(NTH, 2)
narx_kernel(const float* __restrict__ X, const float* __restrict__ y0,
            const float* __restrict__ W1, const float* __restrict__ b1,
            const float* __restrict__ W2, const float* __restrict__ b2,
            float* __restrict__ out)
{
    extern __shared__ char smem[];
    uint4*  __restrict__ B4   = (uint4*)(smem + SM_B4_OFF);
    float4* __restrict__ cp4  = (float4*)(smem + SM_CP_OFF);
    float*  __restrict__ part = (float*)(smem + SM_PART_OFF);
    float*  __restrict__ Xs   = (float*)(smem + SM_X_OFF);

    const int tid  = threadIdx.x;
    const int w    = tid >> 5;
    const int lane = tid & 31;
    const int lq   = lane & 3;       // quad lane
    const int lg   = lane >> 2;      // group
    const int g    = w & 1;          // row group: rows g*32 .. g*32+31
    const int q    = w >> 1;         // column quarter
    const int ctaB0 = blockIdx.x * BTILE;

    // --- stage B as fp16: entry (ntg, lane_t) holds all 32 k for col ntg*8 + (lane_t>>2),
    //     quad slot lq_t = lane_t&3:  .x = k(2lq,2lq+1), .y = +8, .z = +16, .w = +24 ---
    for (int idx = tid; idx < 2048; idx += NTH) {
        const int lnt = idx & 31;
        const int col = (idx >> 5) * 8 + (lnt >> 2);
        const int kk = (lnt & 3) * 2;
        uint4 bv;
        bv.x = h2u(W1[kk * K_HID + col],        W1[(kk + 1) * K_HID + col]);
        bv.y = h2u(W1[(kk + 8) * K_HID + col],  W1[(kk + 9) * K_HID + col]);
        bv.z = h2u(W1[(kk + 16) * K_HID + col], W1[(kk + 17) * K_HID + col]);
        bv.w = h2u(W1[(kk + 24) * K_HID + col], W1[(kk + 25) * K_HID + col]);
        B4[idx] = bv;
    }
    // --- per-col-pair constants: (b1[c0], b1[c1], w2[c0], w2[c1]) ---
    for (int p = tid; p < K_HID / 2; p += NTH) {
        float4 c;
        c.x = b1[2 * p];
        c.y = b1[2 * p + 1];
        c.z = W2[2 * p];
        c.w = W2[2 * p + 1];
        cp4[p] = c;
    }
    // --- stage X(0) into buffer 0 (raw fp32, coalesced) ---
    #pragma unroll
    for (int k = 0; k < 8; ++k) {
        const int j = tid + k * NTH;
        if (j < XELEMS) {
            const int row = div29(j), col = j - row * F_IN;
            Xs[row * XSTRIDE + col] = __ldg(X + (size_t)(ctaB0 + row) * TF_STR + col);
        }
    }
    __syncthreads();

    // --- per-thread row bindings: 4 rows (rowL0 +0/+8/+16/+24) ---
    const int rowL0 = g * 32 + lg;
    const int rowG0 = ctaB0 + rowL0;
    float* __restrict__ outBase = out + (size_t)rowG0 * T_HOR;

    const float b2v = b2[0];

    float f0a = y0[rowG0 * 3 + 0],        f1a = y0[rowG0 * 3 + 1],        f2a = y0[rowG0 * 3 + 2];
    float f0b = y0[(rowG0 + 8) * 3 + 0],  f1b = y0[(rowG0 + 8) * 3 + 1],  f2b = y0[(rowG0 + 8) * 3 + 2];
    float f0c = y0[(rowG0 + 16) * 3 + 0], f1c = y0[(rowG0 + 16) * 3 + 1], f2c = y0[(rowG0 + 16) * 3 + 2];
    float f0d = y0[(rowG0 + 24) * 3 + 0], f1d = y0[(rowG0 + 24) * 3 + 1], f2d = y0[(rowG0 + 24) * 3 + 2];
    uint32_t fb12a = h2u(f1a, f2a), fb12b = h2u(f1b, f2b);
    uint32_t fb12c = h2u(f1c, f2c), fb12d = h2u(f1d, f2d);

    const int ntOfs = q * 16;

    for (int t = 0; t < T_HOR; ++t) {
        const float* Xc = Xs + (t & 1) * XBUF;

        uint32_t a0[8], a1[8];
        loadA_h(a0, Xc, rowL0,      lq, f0a, f0b, fb12a, fb12b);
        loadA_h(a1, Xc, rowL0 + 16, lq, f0c, f0d, fb12c, fb12d);

        // prefetch next step's X (raw fp32); latency hidden under the nt loop
        float xr[8];
        const bool pf = (t + 1) < T_HOR;
        if (pf) {
            const float* __restrict__ src = X + (size_t)ctaB0 * TF_STR + (t + 1) * F_IN;
            #pragma unroll
            for (int k = 0; k < 8; ++k) {
                const int j = tid + k * NTH;
                if (j < XELEMS) {
                    const int row = div29(j), col = j - row * F_IN;
                    xr[k] = __ldg(src + (size_t)row * TF_STR + col);
                }
            }
        }

        float dotA = 0.0f, dotB = 0.0f, dotC = 0.0f, dotD = 0.0f;

        #pragma unroll 4
        for (int nt = 0; nt < 16; ++nt) {
            const int ntg = ntOfs + nt;
            const float4 qc = cp4[ntg * 4 + lq];
            const uint4 bv = B4[ntg * 32 + lane];
            float d0 = qc.x, d1 = qc.y, d2 = qc.x, d3 = qc.y;   // set0 (bias-init)
            float e0 = qc.x, e1 = qc.y, e2 = qc.x, e3 = qc.y;   // set1
            // chunk0: k 0-15
            MMA_F16(d0, d1, d2, d3, a0[0], a0[1], a0[2], a0[3], bv.x, bv.y);
            MMA_F16(e0, e1, e2, e3, a1[0], a1[1], a1[2], a1[3], bv.x, bv.y);
            // chunk1: k 16-31 (includes feedback)
            MMA_F16(d0, d1, d2, d3, a0[4], a0[5], a0[6], a0[7], bv.z, bv.w);
            MMA_F16(e0, e1, e2, e3, a1[4], a1[5], a1[6], a1[7], bv.z, bv.w);
            dotA = fmaf(tanh_fast(d0), qc.z, dotA);
            dotA = fmaf(tanh_fast(d1), qc.w, dotA);
            dotB = fmaf(tanh_fast(d2), qc.z, dotB);
            dotB = fmaf(tanh_fast(d3), qc.w, dotB);
            dotC = fmaf(tanh_fast(e0), qc.z, dotC);
            dotC = fmaf(tanh_fast(e1), qc.w, dotC);
            dotD = fmaf(tanh_fast(e2), qc.z, dotD);
            dotD = fmaf(tanh_fast(e3), qc.w, dotD);
        }

        // store staged X(t+1)
        if (pf) {
            float* __restrict__ Xn = Xs + ((t + 1) & 1) * XBUF;
            #pragma unroll
            for (int k = 0; k < 8; ++k) {
                const int j = tid + k * NTH;
                if (j < XELEMS) {
                    const int row = div29(j), col = j - row * F_IN;
                    Xn[row * XSTRIDE + col] = xr[k];
                }
            }
        }

        // quad reduce
        dotA += __shfl_xor_sync(0xffffffffu, dotA, 1);
        dotA += __shfl_xor_sync(0xffffffffu, dotA, 2);
        dotB += __shfl_xor_sync(0xffffffffu, dotB, 1);
        dotB += __shfl_xor_sync(0xffffffffu, dotB, 2);
        dotC += __shfl_xor_sync(0xffffffffu, dotC, 1);
        dotC += __shfl_xor_sync(0xffffffffu, dotC, 2);
        dotD += __shfl_xor_sync(0xffffffffu, dotD, 1);
        dotD += __shfl_xor_sync(0xffffffffu, dotD, 2);

        // cross-quarter combine (double-buffered partials, one barrier)
        float* pbuf = part + (t & 1) * 256;
        if (lq == 0) {
            pbuf[q * 64 + rowL0]      = dotA;
            pbuf[q * 64 + rowL0 + 8]  = dotB;
            pbuf[q * 64 + rowL0 + 16] = dotC;
            pbuf[q * 64 + rowL0 + 24] = dotD;
        }
        __syncthreads();
        const float predA = pbuf[rowL0]      + pbuf[64 + rowL0]      + pbuf[128 + rowL0]      + pbuf[192 + rowL0]      + b2v;
        const float predB = pbuf[rowL0 + 8]  + pbuf[64 + rowL0 + 8]  + pbuf[128 + rowL0 + 8]  + pbuf[192 + rowL0 + 8]  + b2v;
        const float predC = pbuf[rowL0 + 16] + pbuf[64 + rowL0 + 16] + pbuf[128 + rowL0 + 16] + pbuf[192 + rowL0 + 16] + b2v;
        const float predD = pbuf[rowL0 + 24] + pbuf[64 + rowL0 + 24] + pbuf[128 + rowL0 + 24] + pbuf[192 + rowL0 + 24] + b2v;
        if (q == 0 && lq == 0) {
            outBase[t]              = predA;
            outBase[8 * T_HOR + t]  = predB;
            outBase[16 * T_HOR + t] = predC;
            outBase[24 * T_HOR + t] = predD;
        }
        // shift feedback: fb2 <- fb1 <- fb0 <- pred; rebuild packed fb halves
        f2a = f1a; f1a = f0a; f0a = predA;
        f2b = f1b; f1b = f0b; f0b = predB;
        f2c = f1c; f1c = f0c; f0c = predC;
        f2d = f1d; f1d = f0d; f0d = predD;
        fb12a = h2u(f1a, f2a); fb12b = h2u(f1b, f2b);
        fb12c = h2u(f1c, f2c); fb12d = h2u(f1d, f2d);
    }
}

extern "C" void kernel_launch(void* const* d_in, const int* in_sizes, int n_in,
                              void* d_out, int out_size) {
    const float* X  = (const float*)d_in[0];
    const float* y0 = (const float*)d_in[1];
    const float* W1 = (const float*)d_in[2];
    const float* b1 = (const float*)d_in[3];
    const float* W2 = (const float*)d_in[4];
    const float* b2 = (const float*)d_in[5];
    float* out = (float*)d_out;
    (void)in_sizes; (void)n_in; (void)out_size;

    cudaFuncSetAttribute(narx_kernel, cudaFuncAttributeMaxDynamicSharedMemorySize, SM_TOTAL);
    narx_kernel<<<NCTAS, NTH, SM_TOTAL>>>(X, y0, W1, b1, W2, b2, out);
}

// round 11
// speedup vs baseline: 1.3511x; 1.0507x over previous
#include <cuda_runtime.h>
#include <cuda_fp16.h>
#include <cstdint>

// ---------------- problem constants ----------------
#define B_TOT   16384
#define T_HOR   128
#define F_IN    29
#define K_HID   512
#define BTILE   64
#define NTH     128
#define NCTAS   (B_TOT / BTILE)     // 256
#define TF_STR  (T_HOR * F_IN)      // 3712 floats per batch row

// per-warp X stage: 16 rows x stride 36 fp32 (single-buffered, warp-private)
#define XSTRIDE 36
#define XWARP   (16 * XSTRIDE)      // 576 floats per warp
#define XW_ELEM (16 * F_IN)         // 464 elements per warp per step

// ---------------- shared memory layout ----------------
// B4: 64 n-tiles x 32 lanes x uint4 (8 fp16 = all 32 k for one col) = 32KB
#define SM_B4_OFF   0
#define SM_CP_OFF   32768                         // 256 x float4 = 4KB
#define SM_X_OFF    (SM_CP_OFF + 4096)            // 36864: 4 warps x 576 floats = 9216B
#define SM_TOTAL    (SM_X_OFF + 4 * XWARP * 4)    // 46080 bytes (2 CTAs/SM easily)

static __device__ __forceinline__ float tanh_fast(float z) {
    float h;
    asm("tanh.approx.f32 %0, %1;" : "=f"(h) : "f"(z));
    return h;
}

static __device__ __forceinline__ uint32_t h2u(float lo, float hi) {
    __half2 h = __floats2half2_rn(lo, hi);
    return *reinterpret_cast<uint32_t*>(&h);
}

// non-volatile fp16 MMA m16n8k16, fp32 accum
#define MMA_F16(d0, d1, d2, d3, a0, a1, a2, a3, b0, b1)                        \
    asm("mma.sync.aligned.m16n8k16.row.col.f32.f16.f16.f32 "                   \
        "{%0,%1,%2,%3}, {%4,%5,%6,%7}, {%8,%9}, {%0,%1,%2,%3};"                \
        : "+f"(d0), "+f"(d1), "+f"(d2), "+f"(d3)                               \
        : "r"(a0), "r"(a1), "r"(a2), "r"(a3), "r"(b0), "r"(b1))

// fast div by 29 for j < 16384
static __device__ __forceinline__ int div29(int j) { return (j * 565) >> 14; }

// Build the A fragment set (8 f16x2 regs) for rows (lg, lg+8) of this warp's X stage.
// m16n8k16: a0/a1 = k(2lq,2lq+1) rows lg/lg+8; a2/a3 = +8; a4/a5 = +16; a6/a7 = +24.
// k 28..31: lq==2 -> (x[28], fb0); lq==3 -> (fb1, fb2); lq<2 -> real X cols.
static __device__ __forceinline__ void loadA_h(uint32_t a[8], const float* __restrict__ Xw,
                                               int lg, int lq,
                                               float fb0lo, float fb0hi,
                                               uint32_t fb12lo, uint32_t fb12hi) {
    const float* xA = Xw + lg * XSTRIDE;
    const float* xB = xA + 8 * XSTRIDE;
    const int c = 2 * lq;
    a[0] = h2u(xA[c],      xA[c + 1]);
    a[1] = h2u(xB[c],      xB[c + 1]);
    a[2] = h2u(xA[c + 8],  xA[c + 9]);
    a[3] = h2u(xB[c + 8],  xB[c + 9]);
    a[4] = h2u(xA[c + 16], xA[c + 17]);
    a[5] = h2u(xB[c + 16], xB[c + 17]);
    if (lq < 2) {
        a[6] = h2u(xA[c + 24], xA[c + 25]);
        a[7] = h2u(xB[c + 24], xB[c + 25]);
    } else if (lq == 2) {
        a[6] = h2u(xA[28], fb0lo);
        a[7] = h2u(xB[28], fb0hi);
    } else {
        a[6] = fb12lo;
        a[7] = fb12hi;
    }
}

__global__ void __launch_bounds__(NTH, 2)
narx_kernel(const float* __restrict__ X, const float* __restrict__ y0,
            const float* __restrict__ W1, const float* __restrict__ b1,
            const float* __restrict__ W2, const float* __restrict__ b2,
            float* __restrict__ out)
{
    extern __shared__ char smem[];
    uint4*  __restrict__ B4  = (uint4*)(smem + SM_B4_OFF);
    float4* __restrict__ cp4 = (float4*)(smem + SM_CP_OFF);

    const int tid  = threadIdx.x;
    const int w    = tid >> 5;
    const int lane = tid & 31;
    const int lq   = lane & 3;       // quad lane (col-pair / k selector)
    const int lg   = lane >> 2;      // group (row selector 0..7)
    const int ctaB0 = blockIdx.x * BTILE;

    float* __restrict__ Xw = (float*)(smem + SM_X_OFF) + w * XWARP;  // warp-private

    // --- stage B as fp16: entry (ntg, lane_t): all 32 k for col ntg*8 + (lane_t>>2) ---
    for (int idx = tid; idx < 2048; idx += NTH) {
        const int lnt = idx & 31;
        const int col = (idx >> 5) * 8 + (lnt >> 2);
        const int kk = (lnt & 3) * 2;
        uint4 bv;
        bv.x = h2u(W1[kk * K_HID + col],        W1[(kk + 1) * K_HID + col]);
        bv.y = h2u(W1[(kk + 8) * K_HID + col],  W1[(kk + 9) * K_HID + col]);
        bv.z = h2u(W1[(kk + 16) * K_HID + col], W1[(kk + 17) * K_HID + col]);
        bv.w = h2u(W1[(kk + 24) * K_HID + col], W1[(kk + 25) * K_HID + col]);
        B4[idx] = bv;
    }
    // --- per-col-pair constants: (b1[c0], b1[c1], w2[c0], w2[c1]) ---
    for (int p = tid; p < K_HID / 2; p += NTH) {
        float4 c;
        c.x = b1[2 * p];
        c.y = b1[2 * p + 1];
        c.z = W2[2 * p];
        c.w = W2[2 * p + 1];
        cp4[p] = c;
    }

    // --- X prefetch mapping: warp covers 16 rows x 29 cols = 464 elements ---
    // element j: row = j/29, col = j%29 (scalar LDG -> no alignment constraint;
    // consecutive j -> consecutive addresses within a row -> coalesced sectors)
    const float* __restrict__ Xbase = X + (size_t)(ctaB0 + w * 16) * TF_STR;

    // stage X(0)
    #pragma unroll
    for (int k = 0; k < 15; ++k) {
        const int j = lane + k * 32;
        if (j < XW_ELEM) {
            const int row = div29(j), col = j - row * F_IN;
            Xw[row * XSTRIDE + col] = __ldg(Xbase + (size_t)row * TF_STR + col);
        }
    }
    __syncthreads();     // covers B4/cp4 staging too

    // --- per-thread rows: rowG (lg) and rowG+8, warp-local ---
    const int rowG = ctaB0 + w * 16 + lg;
    float* __restrict__ outA = out + (size_t)rowG * T_HOR;
    float* __restrict__ outB = outA + 8 * T_HOR;

    const float b2v = b2[0];

    float f0a = y0[rowG * 3 + 0],       f1a = y0[rowG * 3 + 1],       f2a = y0[rowG * 3 + 2];
    float f0b = y0[(rowG + 8) * 3 + 0], f1b = y0[(rowG + 8) * 3 + 1], f2b = y0[(rowG + 8) * 3 + 2];
    uint32_t fb12a = h2u(f1a, f2a), fb12b = h2u(f1b, f2b);

    for (int t = 0; t < T_HOR; ++t) {
        uint32_t a[8];
        loadA_h(a, Xw, lg, lq, f0a, f0b, fb12a, fb12b);

        // prefetch X(t+1) into registers (scalar LDG); latency hidden under nt loop
        float xr[15];
        const bool pf = (t + 1) < T_HOR;
        if (pf) {
            const float* __restrict__ src = Xbase + (size_t)(t + 1) * F_IN;
            #pragma unroll
            for (int k = 0; k < 15; ++k) {
                const int j = lane + k * 32;
                if (j < XW_ELEM) {
                    const int row = div29(j), col = j - row * F_IN;
                    xr[k] = __ldg(src + (size_t)row * TF_STR + col);
                }
            }
        }

        float dotA = 0.0f, dotB = 0.0f;

        #pragma unroll 4
        for (int nt = 0; nt < 64; ++nt) {
            const float4 qc = cp4[nt * 4 + lq];
            const uint4 bv = B4[nt * 32 + lane];
            float d0 = qc.x, d1 = qc.y, d2 = qc.x, d3 = qc.y;   // bias-init accum
            MMA_F16(d0, d1, d2, d3, a[0], a[1], a[2], a[3], bv.x, bv.y);
            MMA_F16(d0, d1, d2, d3, a[4], a[5], a[6], a[7], bv.z, bv.w);
            dotA = fmaf(tanh_fast(d0), qc.z, dotA);
            dotA = fmaf(tanh_fast(d1), qc.w, dotA);
            dotB = fmaf(tanh_fast(d2), qc.z, dotB);
            dotB = fmaf(tanh_fast(d3), qc.w, dotB);
        }

        // store staged X(t+1) into the warp-private buffer (reads for step t done)
        if (pf) {
            #pragma unroll
            for (int k = 0; k < 15; ++k) {
                const int j = lane + k * 32;
                if (j < XW_ELEM) {
                    const int row = div29(j), col = j - row * F_IN;
                    Xw[row * XSTRIDE + col] = xr[k];
                }
            }
        }
        __syncwarp();

        // quad reduce -> every quad lane holds full dots for rows lg, lg+8
        dotA += __shfl_xor_sync(0xffffffffu, dotA, 1);
        dotA += __shfl_xor_sync(0xffffffffu, dotA, 2);
        dotB += __shfl_xor_sync(0xffffffffu, dotB, 1);
        dotB += __shfl_xor_sync(0xffffffffu, dotB, 2);
        const float predA = dotA + b2v;
        const float predB = dotB + b2v;
        if (lq == 0) {
            outA[t] = predA;
            outB[t] = predB;
        }
        // shift feedback (thread-local): fb2 <- fb1 <- fb0 <- pred
        f2a = f1a; f1a = f0a; f0a = predA;
        f2b = f1b; f1b = f0b; f0b = predB;
        fb12a = h2u(f1a, f2a);
        fb12b = h2u(f1b, f2b);
    }
}

extern "C" void kernel_launch(void* const* d_in, const int* in_sizes, int n_in,
                              void* d_out, int out_size) {
    const float* X  = (const float*)d_in[0];
    const float* y0 = (const float*)d_in[1];
    const float* W1 = (const float*)d_in[2];
    const float* b1 = (const float*)d_in[3];
    const float* W2 = (const float*)d_in[4];
    const float* b2 = (const float*)d_in[5];
    float* out = (float*)d_out;
    (void)in_sizes; (void)n_in; (void)out_size;

    cudaFuncSetAttribute(narx_kernel, cudaFuncAttributeMaxDynamicSharedMemorySize, SM_TOTAL);
    narx_kernel<<<NCTAS, NTH, SM_TOTAL>>>(X, y0, W1, b1, W2, b2, out);
}

// round 12
// speedup vs baseline: 1.5026x; 1.1121x over previous
#include <cuda_runtime.h>
#include <cuda_fp16.h>
#include <cstdint>

// ---------------- problem constants ----------------
#define B_TOT   16384
#define T_HOR   128
#define F_IN    29
#define K_HID   512
#define BTILE   64
#define NTH     256
#define NCTAS   (B_TOT / BTILE)     // 256
#define TF_STR  (T_HOR * F_IN)      // 3712 floats per batch row

// pair-shared X stage: 16 rows x stride 36 fp32, double-buffered per pair
#define XSTRIDE 36
#define XPAIR   (16 * XSTRIDE)      // 576 floats per buffer
#define XP_ELEM (16 * F_IN)         // 464 elements per step (split between the 2 warps)

// ---------------- shared memory layout ----------------
// B4: 64 n-tiles x 32 lanes x uint4 = 32KB
#define SM_B4_OFF   0
#define SM_CP_OFF   32768                          // 256 x float4 = 4KB
#define SM_PART_OFF (SM_CP_OFF + 4096)             // 36864: 2 x 128 floats = 1KB
#define SM_X_OFF    (SM_PART_OFF + 1024)           // 37888: 4 pairs x 2 x 576 floats
#define SM_TOTAL    (SM_X_OFF + 4 * 2 * XPAIR * 4) // 56320 bytes (2 CTAs/SM)

static __device__ __forceinline__ float tanh_fast(float z) {
    float h;
    asm("tanh.approx.f32 %0, %1;" : "=f"(h) : "f"(z));
    return h;
}

static __device__ __forceinline__ uint32_t h2u(float lo, float hi) {
    __half2 h = __floats2half2_rn(lo, hi);
    return *reinterpret_cast<uint32_t*>(&h);
}

// non-volatile fp16 MMA m16n8k16, fp32 accum
#define MMA_F16(d0, d1, d2, d3, a0, a1, a2, a3, b0, b1)                        \
    asm("mma.sync.aligned.m16n8k16.row.col.f32.f16.f16.f32 "                   \
        "{%0,%1,%2,%3}, {%4,%5,%6,%7}, {%8,%9}, {%0,%1,%2,%3};"                \
        : "+f"(d0), "+f"(d1), "+f"(d2), "+f"(d3)                               \
        : "r"(a0), "r"(a1), "r"(a2), "r"(a3), "r"(b0), "r"(b1))

// pairwise named barrier: 2 warps = 64 threads, id 1..4 per pair
#define BAR_PAIR(id) asm volatile("bar.sync %0, 64;" :: "r"(id) : "memory")

// fast div by 29 for j < 16384
static __device__ __forceinline__ int div29(int j) { return (j * 565) >> 14; }

// Build the A fragment set (8 f16x2 regs) for rows (lg, lg+8) from the pair's X stage.
// m16n8k16: a0/a1 = k(2lq,2lq+1) rows lg/lg+8; a2/a3 = +8; a4/a5 = +16; a6/a7 = +24.
// k 28..31: lq==2 -> (x[28], fb0); lq==3 -> (fb1, fb2).
static __device__ __forceinline__ void loadA_h(uint32_t a[8], const float* __restrict__ Xp,
                                               int lg, int lq,
                                               float fb0lo, float fb0hi,
                                               uint32_t fb12lo, uint32_t fb12hi) {
    const float* xA = Xp + lg * XSTRIDE;
    const float* xB = xA + 8 * XSTRIDE;
    const int c = 2 * lq;
    a[0] = h2u(xA[c],      xA[c + 1]);
    a[1] = h2u(xB[c],      xB[c + 1]);
    a[2] = h2u(xA[c + 8],  xA[c + 9]);
    a[3] = h2u(xB[c + 8],  xB[c + 9]);
    a[4] = h2u(xA[c + 16], xA[c + 17]);
    a[5] = h2u(xB[c + 16], xB[c + 17]);
    if (lq < 2) {
        a[6] = h2u(xA[c + 24], xA[c + 25]);
        a[7] = h2u(xB[c + 24], xB[c + 25]);
    } else if (lq == 2) {
        a[6] = h2u(xA[28], fb0lo);
        a[7] = h2u(xB[28], fb0hi);
    } else {
        a[6] = fb12lo;
        a[7] = fb12hi;
    }
}

__global__ void __launch_bounds__(NTH, 2)
narx_kernel(const float* __restrict__ X, const float* __restrict__ y0,
            const float* __restrict__ W1, const float* __restrict__ b1,
            const float* __restrict__ W2, const float* __restrict__ b2,
            float* __restrict__ out)
{
    extern __shared__ char smem[];
    uint4*  __restrict__ B4   = (uint4*)(smem + SM_B4_OFF);
    float4* __restrict__ cp4  = (float4*)(smem + SM_CP_OFF);
    float*  __restrict__ part = (float*)(smem + SM_PART_OFF);

    const int tid  = threadIdx.x;
    const int w    = tid >> 5;
    const int lane = tid & 31;
    const int lq   = lane & 3;       // quad lane
    const int lg   = lane >> 2;      // group (row selector 0..7)
    const int pr   = w >> 1;         // pair index 0..3 (owns rows pr*16..pr*16+15)
    const int h    = w & 1;          // column half: cols h*256 .. h*256+255
    const int ctaB0 = blockIdx.x * BTILE;

    float* __restrict__ Xpair = (float*)(smem + SM_X_OFF) + pr * (2 * XPAIR);

    // --- stage B as fp16 ---
    for (int idx = tid; idx < 2048; idx += NTH) {
        const int lnt = idx & 31;
        const int col = (idx >> 5) * 8 + (lnt >> 2);
        const int kk = (lnt & 3) * 2;
        uint4 bv;
        bv.x = h2u(W1[kk * K_HID + col],        W1[(kk + 1) * K_HID + col]);
        bv.y = h2u(W1[(kk + 8) * K_HID + col],  W1[(kk + 9) * K_HID + col]);
        bv.z = h2u(W1[(kk + 16) * K_HID + col], W1[(kk + 17) * K_HID + col]);
        bv.w = h2u(W1[(kk + 24) * K_HID + col], W1[(kk + 25) * K_HID + col]);
        B4[idx] = bv;
    }
    // --- per-col-pair constants ---
    for (int p = tid; p < K_HID / 2; p += NTH) {
        float4 c;
        c.x = b1[2 * p];
        c.y = b1[2 * p + 1];
        c.z = W2[2 * p];
        c.w = W2[2 * p + 1];
        cp4[p] = c;
    }

    // --- X staging: warp h stages elements [h*232, h*232+232) of the pair's slice ---
    const float* __restrict__ Xbase = X + (size_t)(ctaB0 + pr * 16) * TF_STR;
    const int jBase = h * 232;

    // stage X(0) into buffer 0
    #pragma unroll
    for (int k = 0; k < 8; ++k) {
        const int j = jBase + lane + k * 32;
        if (lane + k * 32 < 232) {
            const int row = div29(j), col = j - row * F_IN;
            Xpair[row * XSTRIDE + col] = __ldg(Xbase + (size_t)row * TF_STR + col);
        }
    }
    __syncthreads();     // covers B4/cp4/X(0)

    // --- per-thread rows: rowG (lg) and rowG+8 within the pair ---
    const int rowG = ctaB0 + pr * 16 + lg;
    float* __restrict__ outA = out + (size_t)rowG * T_HOR;
    float* __restrict__ outB = outA + 8 * T_HOR;

    const float b2v = b2[0];
    const int barId = 1 + pr;
    const int pBase = pr * 32;           // partial slot base for this pair

    float f0a = y0[rowG * 3 + 0],       f1a = y0[rowG * 3 + 1],       f2a = y0[rowG * 3 + 2];
    float f0b = y0[(rowG + 8) * 3 + 0], f1b = y0[(rowG + 8) * 3 + 1], f2b = y0[(rowG + 8) * 3 + 2];
    uint32_t fb12a = h2u(f1a, f2a), fb12b = h2u(f1b, f2b);

    const int ntOfs = h * 32;            // this warp's 32 n-tiles (256 cols)

    for (int t = 0; t < T_HOR; ++t) {
        const float* Xp = Xpair + (t & 1) * XPAIR;

        uint32_t a[8];
        loadA_h(a, Xp, lg, lq, f0a, f0b, fb12a, fb12b);

        // prefetch this warp's half of X(t+1) (scalar LDG, latency hidden)
        float xr[8];
        const bool pf = (t + 1) < T_HOR;
        if (pf) {
            const float* __restrict__ src = Xbase + (size_t)(t + 1) * F_IN;
            #pragma unroll
            for (int k = 0; k < 8; ++k) {
                if (lane + k * 32 < 232) {
                    const int j = jBase + lane + k * 32;
                    const int row = div29(j), col = j - row * F_IN;
                    xr[k] = __ldg(src + (size_t)row * TF_STR + col);
                }
            }
        }

        float dotA = 0.0f, dotB = 0.0f;

        #pragma unroll 4
        for (int nt = 0; nt < 32; ++nt) {
            const int ntg = ntOfs + nt;
            const float4 qc = cp4[ntg * 4 + lq];
            const uint4 bv = B4[ntg * 32 + lane];
            float d0 = qc.x, d1 = qc.y, d2 = qc.x, d3 = qc.y;   // bias-init accum
            MMA_F16(d0, d1, d2, d3, a[0], a[1], a[2], a[3], bv.x, bv.y);
            MMA_F16(d0, d1, d2, d3, a[4], a[5], a[6], a[7], bv.z, bv.w);
            dotA = fmaf(tanh_fast(d0), qc.z, dotA);
            dotA = fmaf(tanh_fast(d1), qc.w, dotA);
            dotB = fmaf(tanh_fast(d2), qc.z, dotB);
            dotB = fmaf(tanh_fast(d3), qc.w, dotB);
        }

        // store staged X(t+1) into the OTHER buffer (pair-shared; fenced by BAR below)
        if (pf) {
            float* __restrict__ Xn = Xpair + ((t + 1) & 1) * XPAIR;
            #pragma unroll
            for (int k = 0; k < 8; ++k) {
                if (lane + k * 32 < 232) {
                    const int j = jBase + lane + k * 32;
                    const int row = div29(j), col = j - row * F_IN;
                    Xn[row * XSTRIDE + col] = xr[k];
                }
            }
        }

        // quad reduce over this warp's 256 cols
        dotA += __shfl_xor_sync(0xffffffffu, dotA, 1);
        dotA += __shfl_xor_sync(0xffffffffu, dotA, 2);
        dotB += __shfl_xor_sync(0xffffffffu, dotB, 1);
        dotB += __shfl_xor_sync(0xffffffffu, dotB, 2);

        // exchange half-partials with the paired warp (double-buffered by t-parity)
        float* pbuf = part + (t & 1) * 128;
        if (lq == 0) {
            pbuf[pBase + h * 16 + lg]     = dotA;
            pbuf[pBase + h * 16 + lg + 8] = dotB;
        }
        BAR_PAIR(barId);    // drains STS (partials AND X(t+1)); syncs only the pair

        // both halves compute the identical sum lo+hi
        const float predA = pbuf[pBase + lg]     + pbuf[pBase + 16 + lg]     + b2v;
        const float predB = pbuf[pBase + lg + 8] + pbuf[pBase + 16 + lg + 8] + b2v;
        if (h == 0 && lq == 0) {
            outA[t] = predA;
            outB[t] = predB;
        }
        // shift feedback: fb2 <- fb1 <- fb0 <- pred
        f2a = f1a; f1a = f0a; f0a = predA;
        f2b = f1b; f1b = f0b; f0b = predB;
        fb12a = h2u(f1a, f2a);
        fb12b = h2u(f1b, f2b);
    }
}

extern "C" void kernel_launch(void* const* d_in, const int* in_sizes, int n_in,
                              void* d_out, int out_size) {
    const float* X  = (const float*)d_in[0];
    const float* y0 = (const float*)d_in[1];
    const float* W1 = (const float*)d_in[2];
    const float* b1 = (const float*)d_in[3];
    const float* W2 = (const float*)d_in[4];
    const float* b2 = (const float*)d_in[5];
    float* out = (float*)d_out;
    (void)in_sizes; (void)n_in; (void)out_size;

    cudaFuncSetAttribute(narx_kernel, cudaFuncAttributeMaxDynamicSharedMemorySize, SM_TOTAL);
    narx_kernel<<<NCTAS, NTH, SM_TOTAL>>>(X, y0, W1, b1, W2, b2, out);
}

// round 13
// speedup vs baseline: 1.5146x; 1.0080x over previous
#include <cuda_runtime.h>
#include <cuda_fp16.h>
#include <cstdint>

// ---------------- problem constants ----------------
#define B_TOT   16384
#define T_HOR   128
#define F_IN    29
#define K_HID   512
#define BTILE   64
#define NTH     256
#define NCTAS   (B_TOT / BTILE)     // 256
#define TF_STR  (T_HOR * F_IN)      // 3712 floats per batch row

// pair-shared X stage: 16 rows x stride 37 fp32 (conflict-free A-frag LDS), dbl-buffered
#define XSTRIDE 37
#define XPAIR   (16 * XSTRIDE)      // 592 floats per buffer

// ---------------- shared memory layout ----------------
#define SM_B4_OFF   0                               // 64 nt x 32 lanes x uint4 = 32KB
#define SM_B1_OFF   32768                           // 256 x float2 (b1 pairs) = 2KB
#define SM_W2_OFF   (SM_B1_OFF + 2048)              // 34816: 128 x uint2 (w2 f16x2) = 1KB
#define SM_PART_OFF (SM_W2_OFF + 1024)              // 35840: 2 x 128 floats = 1KB
#define SM_X_OFF    (SM_PART_OFF + 1024)            // 36864: 4 pairs x 2 x 592 floats
#define SM_TOTAL    (SM_X_OFF + 4 * 2 * XPAIR * 4)  // 55808 bytes (2 CTAs/SM)

static __device__ __forceinline__ uint32_t h2u(float lo, float hi) {
    __half2 h = __floats2half2_rn(lo, hi);
    return *reinterpret_cast<uint32_t*>(&h);
}

// pack two fp32 -> f16x2 register (lo = first arg)
static __device__ __forceinline__ uint32_t f16x2_of(float lo, float hi) {
    uint32_t r;
    asm("cvt.rn.f16x2.f32 %0, %1, %2;" : "=r"(r) : "f"(hi), "f"(lo));
    return r;
}

// packed fp16 tanh: one MUFU op for 2 elements
static __device__ __forceinline__ uint32_t tanh2(uint32_t z) {
    uint32_t h;
    asm("tanh.approx.f16x2 %0, %1;" : "=r"(h) : "r"(z));
    return h;
}

// non-volatile fp16 MMA m16n8k16, fp32 accum
#define MMA_F16(d0, d1, d2, d3, a0, a1, a2, a3, b0, b1)                        \
    asm("mma.sync.aligned.m16n8k16.row.col.f32.f16.f16.f32 "                   \
        "{%0,%1,%2,%3}, {%4,%5,%6,%7}, {%8,%9}, {%0,%1,%2,%3};"                \
        : "+f"(d0), "+f"(d1), "+f"(d2), "+f"(d3)                               \
        : "r"(a0), "r"(a1), "r"(a2), "r"(a3), "r"(b0), "r"(b1))

// pairwise named barrier: 2 warps = 64 threads
#define BAR_PAIR(id) asm volatile("bar.sync %0, 64;" :: "r"(id) : "memory")

// fast div by 29 for j < 16384
static __device__ __forceinline__ int div29(int j) { return (j * 565) >> 14; }

// Build the A fragment set (8 f16x2 regs) for rows (lg, lg+8) from the pair's X stage.
// k 28..31: lq==2 -> (x[28], fb0); lq==3 -> (fb1, fb2).
static __device__ __forceinline__ void loadA_h(uint32_t a[8], const float* __restrict__ Xp,
                                               int lg, int lq,
                                               float fb0lo, float fb0hi,
                                               uint32_t fb12lo, uint32_t fb12hi) {
    const float* xA = Xp + lg * XSTRIDE;
    const float* xB = xA + 8 * XSTRIDE;
    const int c = 2 * lq;
    a[0] = h2u(xA[c],      xA[c + 1]);
    a[1] = h2u(xB[c],      xB[c + 1]);
    a[2] = h2u(xA[c + 8],  xA[c + 9]);
    a[3] = h2u(xB[c + 8],  xB[c + 9]);
    a[4] = h2u(xA[c + 16], xA[c + 17]);
    a[5] = h2u(xB[c + 16], xB[c + 17]);
    if (lq < 2) {
        a[6] = h2u(xA[c + 24], xA[c + 25]);
        a[7] = h2u(xB[c + 24], xB[c + 25]);
    } else if (lq == 2) {
        a[6] = h2u(xA[28], fb0lo);
        a[7] = h2u(xB[28], fb0hi);
    } else {
        a[6] = fb12lo;
        a[7] = fb12hi;
    }
}

__global__ void __launch_bounds__(NTH, 2)
narx_kernel(const float* __restrict__ X, const float* __restrict__ y0,
            const float* __restrict__ W1, const float* __restrict__ b1,
            const float* __restrict__ W2, const float* __restrict__ b2,
            float* __restrict__ out)
{
    extern __shared__ char smem[];
    uint4*  __restrict__ B4   = (uint4*)(smem + SM_B4_OFF);
    float2* __restrict__ b1sm = (float2*)(smem + SM_B1_OFF);
    uint2*  __restrict__ w2sm = (uint2*)(smem + SM_W2_OFF);
    float*  __restrict__ part = (float*)(smem + SM_PART_OFF);

    const int tid  = threadIdx.x;
    const int w    = tid >> 5;
    const int lane = tid & 31;
    const int lq   = lane & 3;       // quad lane
    const int lg   = lane >> 2;      // group (row selector 0..7)
    const int pr   = w >> 1;         // pair index 0..3
    const int h    = w & 1;          // column half: cols h*256 .. h*256+255
    const int ctaB0 = blockIdx.x * BTILE;

    float* __restrict__ Xpair = (float*)(smem + SM_X_OFF) + pr * (2 * XPAIR);

    // --- stage B (W1, all 32 rows) as fp16 ---
    for (int idx = tid; idx < 2048; idx += NTH) {
        const int lnt = idx & 31;
        const int col = (idx >> 5) * 8 + (lnt >> 2);
        const int kk = (lnt & 3) * 2;
        uint4 bv;
        bv.x = h2u(W1[kk * K_HID + col],        W1[(kk + 1) * K_HID + col]);
        bv.y = h2u(W1[(kk + 8) * K_HID + col],  W1[(kk + 9) * K_HID + col]);
        bv.z = h2u(W1[(kk + 16) * K_HID + col], W1[(kk + 17) * K_HID + col]);
        bv.w = h2u(W1[(kk + 24) * K_HID + col], W1[(kk + 25) * K_HID + col]);
        B4[idx] = bv;
    }
    // --- b1 col-pair constants ---
    for (int p = tid; p < K_HID / 2; p += NTH) {
        float2 c;
        c.x = b1[2 * p];
        c.y = b1[2 * p + 1];
        b1sm[p] = c;
    }
    // --- W2 as f16x2 B-fragments for the dot-MMA ---
    // idx: lq=idx&3, ntp=(idx>>2)&15, hh=idx>>6; col base C=(hh*32+2*ntp)*8
    for (int idx = tid; idx < 128; idx += NTH) {
        const int lqt = idx & 3, ntp = (idx >> 2) & 15, hh = idx >> 6;
        const int C = (hh * 32 + 2 * ntp) * 8;
        uint2 v;
        v.x = h2u(W2[C + 2 * lqt],     W2[C + 2 * lqt + 1]);
        v.y = h2u(W2[C + 2 * lqt + 8], W2[C + 2 * lqt + 9]);
        w2sm[idx] = v;
    }

    // --- X staging: warp h stages elements [h*232, h*232+232) of the pair's slice ---
    const float* __restrict__ Xbase = X + (size_t)(ctaB0 + pr * 16) * TF_STR;
    const int jBase = h * 232;

    #pragma unroll
    for (int k = 0; k < 8; ++k) {
        const int j = jBase + lane + k * 32;
        if (lane + k * 32 < 232) {
            const int row = div29(j), col = j - row * F_IN;
            Xpair[row * XSTRIDE + col] = __ldg(Xbase + (size_t)row * TF_STR + col);
        }
    }
    __syncthreads();

    // --- per-thread rows: rowG (lg) and rowG+8 ---
    const int rowG = ctaB0 + pr * 16 + lg;
    float* __restrict__ outA = out + (size_t)rowG * T_HOR;
    float* __restrict__ outB = outA + 8 * T_HOR;

    const float b2v = b2[0];
    const int barId = 1 + pr;
    const int pBase = pr * 32;

    float f0a = y0[rowG * 3 + 0],       f1a = y0[rowG * 3 + 1],       f2a = y0[rowG * 3 + 2];
    float f0b = y0[(rowG + 8) * 3 + 0], f1b = y0[(rowG + 8) * 3 + 1], f2b = y0[(rowG + 8) * 3 + 2];
    uint32_t fb12a = h2u(f1a, f2a), fb12b = h2u(f1b, f2b);

    const int ntOfs = h * 32;            // this warp's 32 n-tiles (256 cols)
    const int w2Base = h * 64;           // w2sm index base: (h*16+ntp)*4

    for (int t = 0; t < T_HOR; ++t) {
        const float* Xp = Xpair + (t & 1) * XPAIR;

        uint32_t a[8];
        loadA_h(a, Xp, lg, lq, f0a, f0b, fb12a, fb12b);

        // prefetch this warp's half of X(t+1) (scalar LDG, latency hidden)
        float xr[8];
        const bool pf = (t + 1) < T_HOR;
        if (pf) {
            const float* __restrict__ src = Xbase + (size_t)(t + 1) * F_IN;
            #pragma unroll
            for (int k = 0; k < 8; ++k) {
                if (lane + k * 32 < 232) {
                    const int j = jBase + lane + k * 32;
                    const int row = div29(j), col = j - row * F_IN;
                    xr[k] = __ldg(src + (size_t)row * TF_STR + col);
                }
            }
        }

        // dot accumulators (fp32, via dot-MMA); n=0 result lands in lq==0's dt0/dt2
        float dt0 = 0.0f, dt1 = 0.0f, dt2 = 0.0f, dt3 = 0.0f;

        #pragma unroll 2
        for (int ntp = 0; ntp < 16; ++ntp) {
            uint32_t hlo0, hhi0, hlo1, hhi1;
            #pragma unroll
            for (int e = 0; e < 2; ++e) {
                const int ntg = ntOfs + 2 * ntp + e;
                const float2 bb1 = b1sm[ntg * 4 + lq];
                const uint4 bv = B4[ntg * 32 + lane];
                float d0 = bb1.x, d1 = bb1.y, d2 = bb1.x, d3 = bb1.y;  // bias-init
                MMA_F16(d0, d1, d2, d3, a[0], a[1], a[2], a[3], bv.x, bv.y);
                MMA_F16(d0, d1, d2, d3, a[4], a[5], a[6], a[7], bv.z, bv.w);
                const uint32_t hlo = tanh2(f16x2_of(d0, d1));  // rows lg,   cols c0,c1
                const uint32_t hhi = tanh2(f16x2_of(d2, d3));  // rows lg+8, cols c0,c1
                if (e == 0) { hlo0 = hlo; hhi0 = hhi; }
                else        { hlo1 = hlo; hhi1 = hhi; }
            }
            // dot-MMA: A = h (16 rows x k=16 cols), B = w2 in n=0 (lg==0 lanes), D += fp32
            uint32_t w0 = 0, w1 = 0;
            if (lg == 0) {
                const uint2 wv = w2sm[w2Base + ntp * 4 + lq];
                w0 = wv.x; w1 = wv.y;
            }
            MMA_F16(dt0, dt1, dt2, dt3, hlo0, hhi0, hlo1, hhi1, w0, w1);
        }

        // store staged X(t+1) into the other buffer (fenced by BAR below)
        if (pf) {
            float* __restrict__ Xn = Xpair + ((t + 1) & 1) * XPAIR;
            #pragma unroll
            for (int k = 0; k < 8; ++k) {
                if (lane + k * 32 < 232) {
                    const int j = jBase + lane + k * 32;
                    const int row = div29(j), col = j - row * F_IN;
                    Xn[row * XSTRIDE + col] = xr[k];
                }
            }
        }

        // exchange half-dots with the paired warp (lq==0 holds n=0 column)
        float* pbuf = part + (t & 1) * 128;
        if (lq == 0) {
            pbuf[pBase + h * 16 + lg]     = dt0;   // rows lg
            pbuf[pBase + h * 16 + lg + 8] = dt2;   // rows lg+8
        }
        BAR_PAIR(barId);    // drains STS (partials AND X(t+1)); syncs only the pair

        const float predA = pbuf[pBase + lg]     + pbuf[pBase + 16 + lg]     + b2v;
        const float predB = pbuf[pBase + lg + 8] + pbuf[pBase + 16 + lg + 8] + b2v;
        if (h == 0 && lq == 0) {
            outA[t] = predA;
            outB[t] = predB;
        }
        // shift feedback: fb2 <- fb1 <- fb0 <- pred
        f2a = f1a; f1a = f0a; f0a = predA;
        f2b = f1b; f1b = f0b; f0b = predB;
        fb12a = h2u(f1a, f2a);
        fb12b = h2u(f1b, f2b);
    }
}

extern "C" void kernel_launch(void* const* d_in, const int* in_sizes, int n_in,
                              void* d_out, int out_size) {
    const float* X  = (const float*)d_in[0];
    const float* y0 = (const float*)d_in[1];
    const float* W1 = (const float*)d_in[2];
    const float* b1 = (const float*)d_in[3];
    const float* W2 = (const float*)d_in[4];
    const float* b2 = (const float*)d_in[5];
    float* out = (float*)d_out;
    (void)in_sizes; (void)n_in; (void)out_size;

    cudaFuncSetAttribute(narx_kernel, cudaFuncAttributeMaxDynamicSharedMemorySize, SM_TOTAL);
    narx_kernel<<<NCTAS, NTH, SM_TOTAL>>>(X, y0, W1, b1, W2, b2, out);
}